// round 11
// baseline (speedup 1.0000x reference)
#include <cuda_runtime.h>
#include <cuda_bf16.h>
#include <cstdint>

// Problem dims (fixed for this dataset)
#define BB   2
#define SS   2048
#define DD   1024
#define HH   16
#define DHD  64
#define MM   (BB*SS)      // 4096 rows
#define NQKV 3072

// Scratch (allocation-free rule: __device__ globals)
__device__ float          g_QKV[MM*NQKV];     // fused Q|K|V (tf32-rounded), stride 3072
__device__ __nv_bfloat16  g_Xh[MM*DD],  g_Xl[MM*DD];
__device__ __nv_bfloat16  g_Zh[MM*DD],  g_Zl[MM*DD];
__device__ __nv_bfloat16  g_Wth[NQKV*DD], g_Wtl[NQKV*DD];   // W_qkv^T [n][k]
__device__ __nv_bfloat16  g_Woth[DD*DD],  g_Wotl[DD*DD];    // W_O^T   [n][k]
__device__ float          g_bias[NQKV + DD];

// ---------------------------------------------------------------------------
// helpers
// ---------------------------------------------------------------------------
__device__ __forceinline__ void bsplit(float v, __nv_bfloat16 &h, __nv_bfloat16 &l) {
    h = __float2bfloat16_rn(v);
    l = __float2bfloat16_rn(v - __bfloat162float(h));
}
__device__ __forceinline__ uint32_t f2tf(float v) {
    uint32_t r; asm("cvt.rna.tf32.f32 %0, %1;" : "=r"(r) : "f"(v)); return r;
}
__device__ __forceinline__ void mma_tf32(float* d, const uint32_t* a, const uint32_t* b) {
    asm volatile(
        "mma.sync.aligned.m16n8k8.row.col.f32.tf32.tf32.f32 "
        "{%0,%1,%2,%3}, {%4,%5,%6,%7}, {%8,%9}, {%0,%1,%2,%3};\n"
        : "+f"(d[0]), "+f"(d[1]), "+f"(d[2]), "+f"(d[3])
        : "r"(a[0]), "r"(a[1]), "r"(a[2]), "r"(a[3]), "r"(b[0]), "r"(b[1]));
}
__device__ __forceinline__ void mma_bf16(float* d, const uint32_t* a, const uint32_t* b) {
    asm volatile(
        "mma.sync.aligned.m16n8k16.row.col.f32.bf16.bf16.f32 "
        "{%0,%1,%2,%3}, {%4,%5,%6,%7}, {%8,%9}, {%0,%1,%2,%3};\n"
        : "+f"(d[0]), "+f"(d[1]), "+f"(d[2]), "+f"(d[3])
        : "r"(a[0]), "r"(a[1]), "r"(a[2]), "r"(a[3]), "r"(b[0]), "r"(b[1]));
}
__device__ __forceinline__ void ldm4(uint32_t* r, uint32_t addr) {
    asm volatile("ldmatrix.sync.aligned.m8n8.x4.shared.b16 {%0,%1,%2,%3}, [%4];"
                 : "=r"(r[0]), "=r"(r[1]), "=r"(r[2]), "=r"(r[3]) : "r"(addr));
}
__device__ __forceinline__ uint32_t smem_u32(const void* p) {
    uint32_t a;
    asm("{ .reg .u64 t; cvta.to.shared.u64 t, %1; cvt.u32.u64 %0, t; }" : "=r"(a) : "l"(p));
    return a;
}

// ---------------------------------------------------------------------------
// Fused pre-pass: one launch does split_ext / split_wqkv / split_wo / bias_prep
// block ranges: [0,4096) ext, [4096,4864) wqkv, [4864,5120) wo, [5120,5136) bias
// ---------------------------------------------------------------------------
__global__ __launch_bounds__(256) void prep_all(
    const float* __restrict__ x,
    const float* __restrict__ Wq, const float* __restrict__ Wk, const float* __restrict__ Wv,
    const float* __restrict__ Wo,
    const float* __restrict__ bq, const float* __restrict__ bk,
    const float* __restrict__ bv, const float* __restrict__ bo)
{
    __shared__ float sm[64][65];
    const int bx = blockIdx.x;
    const int t  = threadIdx.x;

    if (bx < 4096) {
        // split x -> Xh/Xl
        int i = (bx * 256 + t) * 4;
        float4 v = *(const float4*)&x[i];
        __nv_bfloat16 h0,l0,h1,l1,h2,l2,h3,l3;
        bsplit(v.x,h0,l0); bsplit(v.y,h1,l1); bsplit(v.z,h2,l2); bsplit(v.w,h3,l3);
        *(__nv_bfloat162*)&g_Xh[i]     = __nv_bfloat162(h0,h1);
        *(__nv_bfloat162*)&g_Xh[i + 2] = __nv_bfloat162(h2,h3);
        *(__nv_bfloat162*)&g_Xl[i]     = __nv_bfloat162(l0,l1);
        *(__nv_bfloat162*)&g_Xl[i + 2] = __nv_bfloat162(l2,l3);
    } else if (bx < 4864) {
        // W_{q,k,v}[h][k][d] -> Wt[n][k] hi/lo
        int b2 = bx - 4096;                 // 0..767  (16 k-blocks x 48 n-blocks)
        int k0 = (b2 & 15) * 64;
        int n0 = (b2 >> 4) * 64;
        int which = n0 >> 10;
        int h = (n0 >> 6) & 15;
        const float* __restrict__ W = (which == 0) ? Wq : (which == 1) ? Wk : Wv;
#pragma unroll
        for (int i = 0; i < 16; i++) {
            int idx = t + i * 256;
            int r = idx >> 6, c = idx & 63;
            sm[r][c] = W[h * (DD * DHD) + (k0 + r) * DHD + c];
        }
        __syncthreads();
#pragma unroll
        for (int i = 0; i < 16; i++) {
            int idx = t + i * 256;
            int nl = idx >> 6, kl = idx & 63;
            __nv_bfloat16 hi, lo;
            bsplit(sm[kl][nl], hi, lo);
            g_Wth[(n0 + nl) * DD + k0 + kl] = hi;
            g_Wtl[(n0 + nl) * DD + k0 + kl] = lo;
        }
    } else if (bx < 5120) {
        // W_O [k][n] -> Wot[n][k] hi/lo
        int b2 = bx - 4864;                 // 0..255 (16 x 16)
        int k0 = (b2 & 15) * 64;
        int n0 = (b2 >> 4) * 64;
#pragma unroll
        for (int i = 0; i < 16; i++) {
            int idx = t + i * 256;
            int r = idx >> 6, c = idx & 63;
            sm[r][c] = Wo[(k0 + r) * DD + n0 + c];
        }
        __syncthreads();
#pragma unroll
        for (int i = 0; i < 16; i++) {
            int idx = t + i * 256;
            int nl = idx >> 6, kl = idx & 63;
            __nv_bfloat16 hi, lo;
            bsplit(sm[kl][nl], hi, lo);
            g_Woth[(n0 + nl) * DD + k0 + kl] = hi;
            g_Wotl[(n0 + nl) * DD + k0 + kl] = lo;
        }
    } else {
        int id = (bx - 5120) * 256 + t;     // 0..4095
        if (id < NQKV) {
            int which = id >> 10, n = id & 1023;
            g_bias[id] = (which == 0) ? bq[n] : (which == 1) ? bk[n] : bv[n];
        } else {
            int n = id - NQKV;
            float s = 0.0f;
#pragma unroll
            for (int h = 0; h < HH; h++) s += bo[h * DD + n];
            g_bias[id] = s;
        }
    }
}

// ---------------------------------------------------------------------------
// bf16x3 GEMM: C[m,n] = sum_k A[m,k]*B[n,k] + bias[n]   (K = 1024)
// Block 128x128, BK=32, 8 warps, 3-stage cp.async pipeline, ldmatrix.x4.
// round_out != 0: round stores to tf32 bit patterns (for Q/K/V feeding flash).
// ---------------------------------------------------------------------------
#define GSTG 10240                      // u32 per stage (4 arrays x 128*20)
#define GEMM_SMEM (3 * GSTG * 4)        // 122880 B

__global__ __launch_bounds__(256) void gemm_bf16x3(
    const __nv_bfloat16* __restrict__ Ah, const __nv_bfloat16* __restrict__ Al,
    const __nv_bfloat16* __restrict__ Bh, const __nv_bfloat16* __restrict__ Bl,
    const float* __restrict__ bias, float* __restrict__ C, int ldC, int round_out)
{
    extern __shared__ __align__(16) uint32_t sm[];
    const uint32_t smb = smem_u32(sm);

    const int n0   = blockIdx.x * 128;
    const int m0   = blockIdx.y * 128;
    const int t    = threadIdx.x;
    const int lane = t & 31, w = t >> 5;
    const int g    = lane >> 2, tq = lane & 3;
    const int wm   = w & 1, wn = w >> 1;

    const int a_row_l = ((lane >> 3) & 1) * 8 + (lane & 7);
    const int a_col_l = (lane >> 4) * 4;
    const int b_row_l = (lane >> 4) * 8 + (lane & 7);
    const int b_col_l = ((lane >> 3) & 1) * 4;

    const __nv_bfloat16* srcs[4] = { Ah + (size_t)m0 * DD, Al + (size_t)m0 * DD,
                                     Bh + (size_t)n0 * DD, Bl + (size_t)n0 * DD };

    auto issue = [&](int kt, int s) {
        int k0n = kt * 32;
        uint32_t stoff = (uint32_t)s * GSTG;
#pragma unroll
        for (int i = 0; i < 8; i++) {
            int id = t + i * 256;
            int which = id >> 9, r = (id >> 2) & 127, c = id & 3;
            const __nv_bfloat16* gp = srcs[which] + (size_t)r * DD + k0n + c * 8;
            uint32_t sa = smb + (stoff + which * 2560 + r * 20 + c * 4) * 4;
            asm volatile("cp.async.cg.shared.global [%0], [%1], 16;" :: "r"(sa), "l"(gp));
        }
        asm volatile("cp.async.commit_group;" ::: "memory");
    };

    float acc[4][4][4];
#pragma unroll
    for (int mt = 0; mt < 4; mt++)
#pragma unroll
        for (int nt = 0; nt < 4; nt++)
#pragma unroll
            for (int i = 0; i < 4; i++) acc[mt][nt][i] = 0.0f;

    // prologue: stages 0 and 1 in flight
    issue(0, 0);
    issue(1, 1);

    for (int kt = 0; kt < 32; kt++) {
        // wait until tile kt has arrived (at most 1 newer group may stay in flight)
        if (kt < 31) { asm volatile("cp.async.wait_group 1;" ::: "memory"); }
        else         { asm volatile("cp.async.wait_group 0;" ::: "memory"); }
        __syncthreads();   // tile kt visible to all; compute of kt-1 finished by all

        if (kt + 2 < 32) issue(kt + 2, (kt + 2) % 3);

        const uint32_t st = (uint32_t)(kt % 3) * GSTG;
#pragma unroll
        for (int kk = 0; kk < 2; kk++) {
            uint32_t ah[4][4], al[4][4], bh[2][4], bl[2][4];
#pragma unroll
            for (int mt = 0; mt < 4; mt++) {
                uint32_t off = (st + (wm * 64 + mt * 16 + a_row_l) * 20 + kk * 8 + a_col_l) * 4;
                ldm4(ah[mt], smb + off);
                ldm4(al[mt], smb + off + 2560 * 4);
            }
#pragma unroll
            for (int p = 0; p < 2; p++) {
                uint32_t off = (st + 5120 + (wn * 32 + p * 16 + b_row_l) * 20 + kk * 8 + b_col_l) * 4;
                ldm4(bh[p], smb + off);
                ldm4(bl[p], smb + off + 2560 * 4);
            }
#pragma unroll
            for (int mt = 0; mt < 4; mt++)
#pragma unroll
                for (int nt = 0; nt < 4; nt++)
                    mma_bf16(acc[mt][nt], ah[mt], &bh[nt >> 1][(nt & 1) * 2]);
#pragma unroll
            for (int mt = 0; mt < 4; mt++)
#pragma unroll
                for (int nt = 0; nt < 4; nt++)
                    mma_bf16(acc[mt][nt], ah[mt], &bl[nt >> 1][(nt & 1) * 2]);
#pragma unroll
            for (int mt = 0; mt < 4; mt++)
#pragma unroll
                for (int nt = 0; nt < 4; nt++)
                    mma_bf16(acc[mt][nt], al[mt], &bh[nt >> 1][(nt & 1) * 2]);
        }
    }

#pragma unroll
    for (int mt = 0; mt < 4; mt++) {
        int m = m0 + wm * 64 + mt * 16 + g;
#pragma unroll
        for (int nt = 0; nt < 4; nt++) {
            int n = n0 + wn * 32 + nt * 8 + 2 * tq;
            float b0 = bias[n], b1 = bias[n + 1];
            float v00 = acc[mt][nt][0] + b0, v01 = acc[mt][nt][1] + b1;
            float v10 = acc[mt][nt][2] + b0, v11 = acc[mt][nt][3] + b1;
            if (round_out) {
                v00 = __uint_as_float(f2tf(v00)); v01 = __uint_as_float(f2tf(v01));
                v10 = __uint_as_float(f2tf(v10)); v11 = __uint_as_float(f2tf(v11));
            }
            *(float2*)&C[(size_t)m * ldC + n]       = make_float2(v00, v01);
            *(float2*)&C[(size_t)(m + 8) * ldC + n] = make_float2(v10, v11);
        }
    }
}

// ---------------------------------------------------------------------------
// Flash attention (causal), tf32 mma. 64-row Q tiles, 4 warps (128 thr),
// cp.async double-buffered K/V (raw tf32 bit patterns), 2 CTAs/SM.
// Warp w owns q-rows [w*16, w*16+16). P round-trips via warp-private Ps.
// Epilogue writes hi/lo bf16 split of Z directly.
// ---------------------------------------------------------------------------
#define KSTR 68
#define VSTR 72
#define KVSTG (64*KSTR + 64*VSTR)                 // 8960 u32 per stage
#define FLASH_SMEM ((2*KVSTG + 64*KSTR) * 4)      // 89088 B

__global__ __launch_bounds__(128) void flash_kernel()
{
    extern __shared__ __align__(16) uint32_t sm[];
    uint32_t* Ps = sm + 2 * KVSTG;                // [64][68]

    const int qt = 31 - blockIdx.x;               // big tiles first
    const int h = blockIdx.y, b = blockIdx.z;
    const int t = threadIdx.x, lane = t & 31, w = t >> 5;
    const int g = lane >> 2, tq = lane & 3;
    const float scale = 0.125f;
    const int jc = qt + 1;
    const uint32_t smb = smem_u32(sm);

    const size_t rowbase = (size_t)(b * SS) * NQKV;
    const int qoff = h * 64, koff = 1024 + h * 64, voff = 2048 + h * 64;

    auto issue_kv = [&](int j, int s) {
        uint32_t base = smb + (uint32_t)(s * KVSTG) * 4;
#pragma unroll
        for (int i = 0; i < 16; i++) {
            int id = t + i * 128;                 // 0..2047
            int which = id >> 10;                 // 0=K, 1=V
            int rem = id & 1023;
            int r = rem >> 4, c4 = (rem & 15) * 4;
            const float* gp;
            uint32_t sa;
            if (which == 0) {
                gp = &g_QKV[rowbase + (size_t)(j * 64 + r) * NQKV + koff + c4];
                sa = base + (uint32_t)(r * KSTR + c4) * 4;
            } else {
                gp = &g_QKV[rowbase + (size_t)(j * 64 + r) * NQKV + voff + c4];
                sa = base + (uint32_t)(64 * KSTR + r * VSTR + c4) * 4;
            }
            asm volatile("cp.async.cg.shared.global [%0], [%1], 16;" :: "r"(sa), "l"(gp));
        }
        asm volatile("cp.async.commit_group;" ::: "memory");
    };

    // issue KV tile 0, then load Q (overlapped with the cp.async)
    issue_kv(0, 0);
#pragma unroll
    for (int i = 0; i < 8; i++) {
        int id = t + i * 128;                     // 0..1023
        int r = id >> 4, c4 = (id & 15) * 4;
        uint4 v = *(const uint4*)&g_QKV[rowbase + (size_t)(qt * 64 + r) * NQKV + qoff + c4];
        *(uint4*)&Ps[r * KSTR + c4] = v;
    }
    __syncthreads();

    uint32_t qa[8][4];
    {
        int rb = (w * 16 + g) * KSTR;
#pragma unroll
        for (int kk = 0; kk < 8; kk++) {
            qa[kk][0] = Ps[rb + kk * 8 + tq];
            qa[kk][1] = Ps[rb + 8 * KSTR + kk * 8 + tq];
            qa[kk][2] = Ps[rb + kk * 8 + tq + 4];
            qa[kk][3] = Ps[rb + 8 * KSTR + kk * 8 + tq + 4];
        }
    }

    float m_i[2] = {-1e30f, -1e30f}, l_i[2] = {0.0f, 0.0f};
    float O[8][4];
#pragma unroll
    for (int nt = 0; nt < 8; nt++)
#pragma unroll
        for (int i = 0; i < 4; i++) O[nt][i] = 0.0f;

    for (int j = 0; j < jc; j++) {
        if (j + 1 < jc) {
            issue_kv(j + 1, (j + 1) & 1);
            asm volatile("cp.async.wait_group 1;" ::: "memory");
        } else {
            asm volatile("cp.async.wait_group 0;" ::: "memory");
        }
        __syncthreads();

        const uint32_t* Ks = sm + (j & 1) * KVSTG;
        const uint32_t* Vs = Ks + 64 * KSTR;

        float S[8][4];
#pragma unroll
        for (int nt = 0; nt < 8; nt++)
#pragma unroll
            for (int i = 0; i < 4; i++) S[nt][i] = 0.0f;

#pragma unroll
        for (int kk = 0; kk < 8; kk++) {
#pragma unroll
            for (int nt = 0; nt < 8; nt++) {
                uint32_t kb[2];
                kb[0] = Ks[(nt * 8 + g) * KSTR + kk * 8 + tq];
                kb[1] = Ks[(nt * 8 + g) * KSTR + kk * 8 + tq + 4];
                mma_tf32(S[nt], qa[kk], kb);
            }
        }

        if (j == qt) {
            int r0 = w * 16 + g, r1 = r0 + 8;
#pragma unroll
            for (int nt = 0; nt < 8; nt++) {
                int c = nt * 8 + 2 * tq;
                S[nt][0] = (c     <= r0) ? S[nt][0] * scale : -1e30f;
                S[nt][1] = (c + 1 <= r0) ? S[nt][1] * scale : -1e30f;
                S[nt][2] = (c     <= r1) ? S[nt][2] * scale : -1e30f;
                S[nt][3] = (c + 1 <= r1) ? S[nt][3] * scale : -1e30f;
            }
        } else {
#pragma unroll
            for (int nt = 0; nt < 8; nt++)
#pragma unroll
                for (int i = 0; i < 4; i++) S[nt][i] *= scale;
        }

        float mx0 = -1e30f, mx1 = -1e30f;
#pragma unroll
        for (int nt = 0; nt < 8; nt++) {
            mx0 = fmaxf(mx0, fmaxf(S[nt][0], S[nt][1]));
            mx1 = fmaxf(mx1, fmaxf(S[nt][2], S[nt][3]));
        }
        mx0 = fmaxf(mx0, __shfl_xor_sync(0xffffffffu, mx0, 1));
        mx0 = fmaxf(mx0, __shfl_xor_sync(0xffffffffu, mx0, 2));
        mx1 = fmaxf(mx1, __shfl_xor_sync(0xffffffffu, mx1, 1));
        mx1 = fmaxf(mx1, __shfl_xor_sync(0xffffffffu, mx1, 2));

        float mn0 = fmaxf(m_i[0], mx0), mn1 = fmaxf(m_i[1], mx1);
        float c0 = __expf(m_i[0] - mn0), c1 = __expf(m_i[1] - mn1);
        m_i[0] = mn0; m_i[1] = mn1;

        float rs0 = 0.0f, rs1 = 0.0f;
#pragma unroll
        for (int nt = 0; nt < 8; nt++) {
            float p0 = __expf(S[nt][0] - mn0);
            float p1 = __expf(S[nt][1] - mn0);
            float p2 = __expf(S[nt][2] - mn1);
            float p3 = __expf(S[nt][3] - mn1);
            rs0 += p0 + p1; rs1 += p2 + p3;
            int cb = nt * 8 + 2 * tq;
            *(uint2*)&Ps[(w * 16 + g) * KSTR + cb]     = make_uint2(f2tf(p0), f2tf(p1));
            *(uint2*)&Ps[(w * 16 + g + 8) * KSTR + cb] = make_uint2(f2tf(p2), f2tf(p3));
        }
        rs0 += __shfl_xor_sync(0xffffffffu, rs0, 1);
        rs0 += __shfl_xor_sync(0xffffffffu, rs0, 2);
        rs1 += __shfl_xor_sync(0xffffffffu, rs1, 1);
        rs1 += __shfl_xor_sync(0xffffffffu, rs1, 2);

        l_i[0] = l_i[0] * c0 + rs0;
        l_i[1] = l_i[1] * c1 + rs1;
#pragma unroll
        for (int nt = 0; nt < 8; nt++) {
            O[nt][0] *= c0; O[nt][1] *= c0;
            O[nt][2] *= c1; O[nt][3] *= c1;
        }
        __syncwarp();   // P visible within warp (Ps rows are warp-private)

#pragma unroll
        for (int kk = 0; kk < 8; kk++) {
            uint32_t pa[4];
            int rb = (w * 16 + g) * KSTR + kk * 8;
            pa[0] = Ps[rb + tq];
            pa[1] = Ps[rb + 8 * KSTR + tq];
            pa[2] = Ps[rb + tq + 4];
            pa[3] = Ps[rb + 8 * KSTR + tq + 4];
#pragma unroll
            for (int nt = 0; nt < 8; nt++) {
                uint32_t vb[2];
                vb[0] = Vs[(kk * 8 + tq) * VSTR + nt * 8 + g];
                vb[1] = Vs[(kk * 8 + tq + 4) * VSTR + nt * 8 + g];
                mma_tf32(O[nt], pa, vb);
            }
        }
        __syncthreads();   // protect this stage before next iter's issue overwrites it
    }

    // Epilogue: normalize, write hi/lo bf16 split of Z directly
    float inv0 = 1.0f / l_i[0], inv1 = 1.0f / l_i[1];
    int m = b * SS + qt * 64 + w * 16 + g;
#pragma unroll
    for (int nt = 0; nt < 8; nt++) {
        int c = h * 64 + nt * 8 + 2 * tq;
        float v00 = O[nt][0] * inv0, v01 = O[nt][1] * inv0;
        float v10 = O[nt][2] * inv1, v11 = O[nt][3] * inv1;
        __nv_bfloat16 h00,l00,h01,l01,h10,l10,h11,l11;
        bsplit(v00,h00,l00); bsplit(v01,h01,l01);
        bsplit(v10,h10,l10); bsplit(v11,h11,l11);
        *(__nv_bfloat162*)&g_Zh[(size_t)m * DD + c]       = __nv_bfloat162(h00,h01);
        *(__nv_bfloat162*)&g_Zl[(size_t)m * DD + c]       = __nv_bfloat162(l00,l01);
        *(__nv_bfloat162*)&g_Zh[(size_t)(m + 8) * DD + c] = __nv_bfloat162(h10,h11);
        *(__nv_bfloat162*)&g_Zl[(size_t)(m + 8) * DD + c] = __nv_bfloat162(l10,l11);
    }
}

// ---------------------------------------------------------------------------
extern "C" void kernel_launch(void* const* d_in, const int* in_sizes, int n_in,
                              void* d_out, int out_size)
{
    (void)in_sizes; (void)n_in; (void)out_size;
    const float* x  = (const float*)d_in[0];
    const float* Wq = (const float*)d_in[1];
    const float* bq = (const float*)d_in[2];
    const float* Wk = (const float*)d_in[3];
    const float* bk = (const float*)d_in[4];
    const float* Wv = (const float*)d_in[5];
    const float* Wo = (const float*)d_in[6];
    const float* bv = (const float*)d_in[7];
    const float* bo = (const float*)d_in[8];
    float* out = (float*)d_out;

    cudaFuncSetAttribute(flash_kernel,
                         cudaFuncAttributeMaxDynamicSharedMemorySize, FLASH_SMEM);
    cudaFuncSetAttribute(gemm_bf16x3,
                         cudaFuncAttributeMaxDynamicSharedMemorySize, GEMM_SMEM);

    __nv_bfloat16 *Xh, *Xl, *Wth, *Wtl, *Zh, *Zl, *Woth, *Wotl;
    float *bias_d, *qkv_d;
    cudaGetSymbolAddress((void**)&Xh,   g_Xh);
    cudaGetSymbolAddress((void**)&Xl,   g_Xl);
    cudaGetSymbolAddress((void**)&Wth,  g_Wth);
    cudaGetSymbolAddress((void**)&Wtl,  g_Wtl);
    cudaGetSymbolAddress((void**)&Zh,   g_Zh);
    cudaGetSymbolAddress((void**)&Zl,   g_Zl);
    cudaGetSymbolAddress((void**)&Woth, g_Woth);
    cudaGetSymbolAddress((void**)&Wotl, g_Wotl);
    cudaGetSymbolAddress((void**)&bias_d, g_bias);
    cudaGetSymbolAddress((void**)&qkv_d,  g_QKV);

    // fused pre-pass
    prep_all<<<5136, 256>>>(x, Wq, Wk, Wv, Wo, bq, bk, bv, bo);

    // QKV projection (outputs rounded to tf32 bit patterns)
    gemm_bf16x3<<<dim3(24, 32), 256, GEMM_SMEM>>>(Xh, Xl, Wth, Wtl, bias_d, qkv_d, NQKV, 1);
    // attention (writes Zh/Zl split directly)
    flash_kernel<<<dim3(32, HH, BB), 128, FLASH_SMEM>>>();
    // output projection
    gemm_bf16x3<<<dim3(8, 32), 256, GEMM_SMEM>>>(Zh, Zl, Woth, Wotl, bias_d + NQKV, out, DD, 0);
}

// round 16
// speedup vs baseline: 1.1282x; 1.1282x over previous
#include <cuda_runtime.h>
#include <cuda_bf16.h>
#include <cstdint>

// Problem dims (fixed for this dataset)
#define BB   2
#define SS   2048
#define DD   1024
#define HH   16
#define DHD  64
#define MM   (BB*SS)      // 4096 rows
#define NQKV 3072

// Scratch (allocation-free rule: __device__ globals)
__device__ float          g_QKV[MM*NQKV];     // fused Q|K|V (tf32-rounded), stride 3072
__device__ __nv_bfloat16  g_Xh[MM*DD],  g_Xl[MM*DD];
__device__ __nv_bfloat16  g_Zh[MM*DD],  g_Zl[MM*DD];
__device__ __nv_bfloat16  g_Wth[NQKV*DD], g_Wtl[NQKV*DD];   // W_qkv^T [n][k]
__device__ __nv_bfloat16  g_Woth[DD*DD],  g_Wotl[DD*DD];    // W_O^T   [n][k]
__device__ float          g_bias[NQKV + DD];

// ---------------------------------------------------------------------------
// helpers
// ---------------------------------------------------------------------------
__device__ __forceinline__ void bsplit(float v, __nv_bfloat16 &h, __nv_bfloat16 &l) {
    h = __float2bfloat16_rn(v);
    l = __float2bfloat16_rn(v - __bfloat162float(h));
}
__device__ __forceinline__ uint32_t f2tf(float v) {
    uint32_t r; asm("cvt.rna.tf32.f32 %0, %1;" : "=r"(r) : "f"(v)); return r;
}
__device__ __forceinline__ void mma_tf32(float* d, const uint32_t* a, const uint32_t* b) {
    asm volatile(
        "mma.sync.aligned.m16n8k8.row.col.f32.tf32.tf32.f32 "
        "{%0,%1,%2,%3}, {%4,%5,%6,%7}, {%8,%9}, {%0,%1,%2,%3};\n"
        : "+f"(d[0]), "+f"(d[1]), "+f"(d[2]), "+f"(d[3])
        : "r"(a[0]), "r"(a[1]), "r"(a[2]), "r"(a[3]), "r"(b[0]), "r"(b[1]));
}
__device__ __forceinline__ void mma_bf16(float* d, const uint32_t* a, const uint32_t* b) {
    asm volatile(
        "mma.sync.aligned.m16n8k16.row.col.f32.bf16.bf16.f32 "
        "{%0,%1,%2,%3}, {%4,%5,%6,%7}, {%8,%9}, {%0,%1,%2,%3};\n"
        : "+f"(d[0]), "+f"(d[1]), "+f"(d[2]), "+f"(d[3])
        : "r"(a[0]), "r"(a[1]), "r"(a[2]), "r"(a[3]), "r"(b[0]), "r"(b[1]));
}
__device__ __forceinline__ void ldm4(uint32_t* r, uint32_t addr) {
    asm volatile("ldmatrix.sync.aligned.m8n8.x4.shared.b16 {%0,%1,%2,%3}, [%4];"
                 : "=r"(r[0]), "=r"(r[1]), "=r"(r[2]), "=r"(r[3]) : "r"(addr));
}
__device__ __forceinline__ uint32_t smem_u32(const void* p) {
    uint32_t a;
    asm("{ .reg .u64 t; cvta.to.shared.u64 t, %1; cvt.u32.u64 %0, t; }" : "=r"(a) : "l"(p));
    return a;
}

// ---------------------------------------------------------------------------
// Fused pre-pass: split_ext / split_wqkv / split_wo / bias_prep in one launch
// block ranges: [0,4096) ext, [4096,4864) wqkv, [4864,5120) wo, [5120,5136) bias
// ---------------------------------------------------------------------------
__global__ __launch_bounds__(256) void prep_all(
    const float* __restrict__ x,
    const float* __restrict__ Wq, const float* __restrict__ Wk, const float* __restrict__ Wv,
    const float* __restrict__ Wo,
    const float* __restrict__ bq, const float* __restrict__ bk,
    const float* __restrict__ bv, const float* __restrict__ bo)
{
    __shared__ float sm[64][65];
    const int bx = blockIdx.x;
    const int t  = threadIdx.x;

    if (bx < 4096) {
        int i = (bx * 256 + t) * 4;
        float4 v = *(const float4*)&x[i];
        __nv_bfloat16 h0,l0,h1,l1,h2,l2,h3,l3;
        bsplit(v.x,h0,l0); bsplit(v.y,h1,l1); bsplit(v.z,h2,l2); bsplit(v.w,h3,l3);
        *(__nv_bfloat162*)&g_Xh[i]     = __nv_bfloat162(h0,h1);
        *(__nv_bfloat162*)&g_Xh[i + 2] = __nv_bfloat162(h2,h3);
        *(__nv_bfloat162*)&g_Xl[i]     = __nv_bfloat162(l0,l1);
        *(__nv_bfloat162*)&g_Xl[i + 2] = __nv_bfloat162(l2,l3);
    } else if (bx < 4864) {
        int b2 = bx - 4096;                 // 16 k-blocks x 48 n-blocks
        int k0 = (b2 & 15) * 64;
        int n0 = (b2 >> 4) * 64;
        int which = n0 >> 10;
        int h = (n0 >> 6) & 15;
        const float* __restrict__ W = (which == 0) ? Wq : (which == 1) ? Wk : Wv;
#pragma unroll
        for (int i = 0; i < 16; i++) {
            int idx = t + i * 256;
            int r = idx >> 6, c = idx & 63;
            sm[r][c] = W[h * (DD * DHD) + (k0 + r) * DHD + c];
        }
        __syncthreads();
#pragma unroll
        for (int i = 0; i < 16; i++) {
            int idx = t + i * 256;
            int nl = idx >> 6, kl = idx & 63;
            __nv_bfloat16 hi, lo;
            bsplit(sm[kl][nl], hi, lo);
            g_Wth[(n0 + nl) * DD + k0 + kl] = hi;
            g_Wtl[(n0 + nl) * DD + k0 + kl] = lo;
        }
    } else if (bx < 5120) {
        int b2 = bx - 4864;                 // 16 x 16
        int k0 = (b2 & 15) * 64;
        int n0 = (b2 >> 4) * 64;
#pragma unroll
        for (int i = 0; i < 16; i++) {
            int idx = t + i * 256;
            int r = idx >> 6, c = idx & 63;
            sm[r][c] = Wo[(k0 + r) * DD + n0 + c];
        }
        __syncthreads();
#pragma unroll
        for (int i = 0; i < 16; i++) {
            int idx = t + i * 256;
            int nl = idx >> 6, kl = idx & 63;
            __nv_bfloat16 hi, lo;
            bsplit(sm[kl][nl], hi, lo);
            g_Woth[(n0 + nl) * DD + k0 + kl] = hi;
            g_Wotl[(n0 + nl) * DD + k0 + kl] = lo;
        }
    } else {
        int id = (bx - 5120) * 256 + t;     // 0..4095
        if (id < NQKV) {
            int which = id >> 10, n = id & 1023;
            g_bias[id] = (which == 0) ? bq[n] : (which == 1) ? bk[n] : bv[n];
        } else {
            int n = id - NQKV;
            float s = 0.0f;
#pragma unroll
            for (int h = 0; h < HH; h++) s += bo[h * DD + n];
            g_bias[id] = s;
        }
    }
}

// ---------------------------------------------------------------------------
// bf16x3 GEMM: C[m,n] = sum_k A[m,k]*B[n,k] + bias[n]   (K = 1024)
// Block 128x128, BK=32, 8 warps, cp.async double buffer, ldmatrix.x4.
// __launch_bounds__(256, 2): 2 CTAs/SM (64K regs + 160KB smem fit exactly).
// round_out != 0: round stores to tf32 bit patterns (for Q/K/V feeding flash).
// ---------------------------------------------------------------------------
#define GSTG 10240                      // u32 per stage (4 arrays x 128*20)
#define GEMM_SMEM (2 * GSTG * 4)        // 81920 B

__global__ __launch_bounds__(256, 2) void gemm_bf16x3(
    const __nv_bfloat16* __restrict__ Ah, const __nv_bfloat16* __restrict__ Al,
    const __nv_bfloat16* __restrict__ Bh, const __nv_bfloat16* __restrict__ Bl,
    const float* __restrict__ bias, float* __restrict__ C, int ldC, int round_out)
{
    extern __shared__ __align__(16) uint32_t sm[];
    const uint32_t smb = smem_u32(sm);

    const int n0   = blockIdx.x * 128;
    const int m0   = blockIdx.y * 128;
    const int t    = threadIdx.x;
    const int lane = t & 31, w = t >> 5;
    const int g    = lane >> 2, tq = lane & 3;
    const int wm   = w & 1, wn = w >> 1;

    const int a_row_l = ((lane >> 3) & 1) * 8 + (lane & 7);
    const int a_col_l = (lane >> 4) * 4;
    const int b_row_l = (lane >> 4) * 8 + (lane & 7);
    const int b_col_l = ((lane >> 3) & 1) * 4;

    const __nv_bfloat16* srcs[4] = { Ah + (size_t)m0 * DD, Al + (size_t)m0 * DD,
                                     Bh + (size_t)n0 * DD, Bl + (size_t)n0 * DD };

    float acc[4][4][4];
#pragma unroll
    for (int mt = 0; mt < 4; mt++)
#pragma unroll
        for (int nt = 0; nt < 4; nt++)
#pragma unroll
            for (int i = 0; i < 4; i++) acc[mt][nt][i] = 0.0f;

#pragma unroll
    for (int i = 0; i < 8; i++) {
        int id = t + i * 256;
        int which = id >> 9, r = (id >> 2) & 127, c = id & 3;
        const __nv_bfloat16* gp = srcs[which] + (size_t)r * DD + c * 8;
        uint32_t sa = smb + (which * 2560 + r * 20 + c * 4) * 4;
        asm volatile("cp.async.cg.shared.global [%0], [%1], 16;" :: "r"(sa), "l"(gp));
    }
    asm volatile("cp.async.commit_group;" ::: "memory");

    for (int kt = 0; kt < 32; kt++) {
        asm volatile("cp.async.wait_group 0;" ::: "memory");
        __syncthreads();

        if (kt + 1 < 32) {
            int k0n = (kt + 1) * 32;
            uint32_t stoff = ((kt + 1) & 1) * GSTG;
#pragma unroll
            for (int i = 0; i < 8; i++) {
                int id = t + i * 256;
                int which = id >> 9, r = (id >> 2) & 127, c = id & 3;
                const __nv_bfloat16* gp = srcs[which] + (size_t)r * DD + k0n + c * 8;
                uint32_t sa = smb + (stoff + which * 2560 + r * 20 + c * 4) * 4;
                asm volatile("cp.async.cg.shared.global [%0], [%1], 16;" :: "r"(sa), "l"(gp));
            }
            asm volatile("cp.async.commit_group;" ::: "memory");
        }

        const uint32_t st = (kt & 1) * GSTG;
#pragma unroll
        for (int kk = 0; kk < 2; kk++) {
            uint32_t ah[4][4], al[4][4], bh[2][4], bl[2][4];
#pragma unroll
            for (int mt = 0; mt < 4; mt++) {
                uint32_t off = (st + (wm * 64 + mt * 16 + a_row_l) * 20 + kk * 8 + a_col_l) * 4;
                ldm4(ah[mt], smb + off);
                ldm4(al[mt], smb + off + 2560 * 4);
            }
#pragma unroll
            for (int p = 0; p < 2; p++) {
                uint32_t off = (st + 5120 + (wn * 32 + p * 16 + b_row_l) * 20 + kk * 8 + b_col_l) * 4;
                ldm4(bh[p], smb + off);
                ldm4(bl[p], smb + off + 2560 * 4);
            }
#pragma unroll
            for (int mt = 0; mt < 4; mt++)
#pragma unroll
                for (int nt = 0; nt < 4; nt++)
                    mma_bf16(acc[mt][nt], ah[mt], &bh[nt >> 1][(nt & 1) * 2]);
#pragma unroll
            for (int mt = 0; mt < 4; mt++)
#pragma unroll
                for (int nt = 0; nt < 4; nt++)
                    mma_bf16(acc[mt][nt], ah[mt], &bl[nt >> 1][(nt & 1) * 2]);
#pragma unroll
            for (int mt = 0; mt < 4; mt++)
#pragma unroll
                for (int nt = 0; nt < 4; nt++)
                    mma_bf16(acc[mt][nt], al[mt], &bh[nt >> 1][(nt & 1) * 2]);
        }
    }

#pragma unroll
    for (int mt = 0; mt < 4; mt++) {
        int m = m0 + wm * 64 + mt * 16 + g;
#pragma unroll
        for (int nt = 0; nt < 4; nt++) {
            int n = n0 + wn * 32 + nt * 8 + 2 * tq;
            float b0 = bias[n], b1 = bias[n + 1];
            float v00 = acc[mt][nt][0] + b0, v01 = acc[mt][nt][1] + b1;
            float v10 = acc[mt][nt][2] + b0, v11 = acc[mt][nt][3] + b1;
            if (round_out) {
                v00 = __uint_as_float(f2tf(v00)); v01 = __uint_as_float(f2tf(v01));
                v10 = __uint_as_float(f2tf(v10)); v11 = __uint_as_float(f2tf(v11));
            }
            *(float2*)&C[(size_t)m * ldC + n]       = make_float2(v00, v01);
            *(float2*)&C[(size_t)(m + 8) * ldC + n] = make_float2(v10, v11);
        }
    }
}

// ---------------------------------------------------------------------------
// Flash attention (causal), tf32 mma. 64-row Q tiles, 4 warps (128 thr),
// cp.async double-buffered K/V (raw tf32 bit patterns), 2 CTAs/SM.
// Warp w owns q-rows [w*16, w*16+16). P round-trips via warp-private Ps.
// Epilogue writes hi/lo bf16 split of Z directly.
// ---------------------------------------------------------------------------
#define KSTR 68
#define VSTR 72
#define KVSTG (64*KSTR + 64*VSTR)                 // 8960 u32 per stage
#define FLASH_SMEM ((2*KVSTG + 64*KSTR) * 4)      // 89088 B

__global__ __launch_bounds__(128, 2) void flash_kernel()
{
    extern __shared__ __align__(16) uint32_t sm[];
    uint32_t* Ps = sm + 2 * KVSTG;                // [64][68]

    const int qt = 31 - blockIdx.x;               // big tiles first
    const int h = blockIdx.y, b = blockIdx.z;
    const int t = threadIdx.x, lane = t & 31, w = t >> 5;
    const int g = lane >> 2, tq = lane & 3;
    const float scale = 0.125f;
    const int jc = qt + 1;
    const uint32_t smb = smem_u32(sm);

    const size_t rowbase = (size_t)(b * SS) * NQKV;
    const int qoff = h * 64, koff = 1024 + h * 64, voff = 2048 + h * 64;

    auto issue_kv = [&](int j, int s) {
        uint32_t base = smb + (uint32_t)(s * KVSTG) * 4;
#pragma unroll
        for (int i = 0; i < 16; i++) {
            int id = t + i * 128;                 // 0..2047
            int which = id >> 10;                 // 0=K, 1=V
            int rem = id & 1023;
            int r = rem >> 4, c4 = (rem & 15) * 4;
            const float* gp;
            uint32_t sa;
            if (which == 0) {
                gp = &g_QKV[rowbase + (size_t)(j * 64 + r) * NQKV + koff + c4];
                sa = base + (uint32_t)(r * KSTR + c4) * 4;
            } else {
                gp = &g_QKV[rowbase + (size_t)(j * 64 + r) * NQKV + voff + c4];
                sa = base + (uint32_t)(64 * KSTR + r * VSTR + c4) * 4;
            }
            asm volatile("cp.async.cg.shared.global [%0], [%1], 16;" :: "r"(sa), "l"(gp));
        }
        asm volatile("cp.async.commit_group;" ::: "memory");
    };

    // issue KV tile 0, then load Q (overlapped with the cp.async)
    issue_kv(0, 0);
#pragma unroll
    for (int i = 0; i < 8; i++) {
        int id = t + i * 128;                     // 0..1023
        int r = id >> 4, c4 = (id & 15) * 4;
        uint4 v = *(const uint4*)&g_QKV[rowbase + (size_t)(qt * 64 + r) * NQKV + qoff + c4];
        *(uint4*)&Ps[r * KSTR + c4] = v;
    }
    __syncthreads();

    uint32_t qa[8][4];
    {
        int rb = (w * 16 + g) * KSTR;
#pragma unroll
        for (int kk = 0; kk < 8; kk++) {
            qa[kk][0] = Ps[rb + kk * 8 + tq];
            qa[kk][1] = Ps[rb + 8 * KSTR + kk * 8 + tq];
            qa[kk][2] = Ps[rb + kk * 8 + tq + 4];
            qa[kk][3] = Ps[rb + 8 * KSTR + kk * 8 + tq + 4];
        }
    }

    float m_i[2] = {-1e30f, -1e30f}, l_i[2] = {0.0f, 0.0f};
    float O[8][4];
#pragma unroll
    for (int nt = 0; nt < 8; nt++)
#pragma unroll
        for (int i = 0; i < 4; i++) O[nt][i] = 0.0f;

    for (int j = 0; j < jc; j++) {
        if (j + 1 < jc) {
            issue_kv(j + 1, (j + 1) & 1);
            asm volatile("cp.async.wait_group 1;" ::: "memory");
        } else {
            asm volatile("cp.async.wait_group 0;" ::: "memory");
        }
        __syncthreads();

        const uint32_t* Ks = sm + (j & 1) * KVSTG;
        const uint32_t* Vs = Ks + 64 * KSTR;

        float S[8][4];
#pragma unroll
        for (int nt = 0; nt < 8; nt++)
#pragma unroll
            for (int i = 0; i < 4; i++) S[nt][i] = 0.0f;

#pragma unroll
        for (int kk = 0; kk < 8; kk++) {
#pragma unroll
            for (int nt = 0; nt < 8; nt++) {
                uint32_t kb[2];
                kb[0] = Ks[(nt * 8 + g) * KSTR + kk * 8 + tq];
                kb[1] = Ks[(nt * 8 + g) * KSTR + kk * 8 + tq + 4];
                mma_tf32(S[nt], qa[kk], kb);
            }
        }

        if (j == qt) {
            int r0 = w * 16 + g, r1 = r0 + 8;
#pragma unroll
            for (int nt = 0; nt < 8; nt++) {
                int c = nt * 8 + 2 * tq;
                S[nt][0] = (c     <= r0) ? S[nt][0] * scale : -1e30f;
                S[nt][1] = (c + 1 <= r0) ? S[nt][1] * scale : -1e30f;
                S[nt][2] = (c     <= r1) ? S[nt][2] * scale : -1e30f;
                S[nt][3] = (c + 1 <= r1) ? S[nt][3] * scale : -1e30f;
            }
        } else {
#pragma unroll
            for (int nt = 0; nt < 8; nt++)
#pragma unroll
                for (int i = 0; i < 4; i++) S[nt][i] *= scale;
        }

        float mx0 = -1e30f, mx1 = -1e30f;
#pragma unroll
        for (int nt = 0; nt < 8; nt++) {
            mx0 = fmaxf(mx0, fmaxf(S[nt][0], S[nt][1]));
            mx1 = fmaxf(mx1, fmaxf(S[nt][2], S[nt][3]));
        }
        mx0 = fmaxf(mx0, __shfl_xor_sync(0xffffffffu, mx0, 1));
        mx0 = fmaxf(mx0, __shfl_xor_sync(0xffffffffu, mx0, 2));
        mx1 = fmaxf(mx1, __shfl_xor_sync(0xffffffffu, mx1, 1));
        mx1 = fmaxf(mx1, __shfl_xor_sync(0xffffffffu, mx1, 2));

        float mn0 = fmaxf(m_i[0], mx0), mn1 = fmaxf(m_i[1], mx1);
        float c0 = __expf(m_i[0] - mn0), c1 = __expf(m_i[1] - mn1);
        m_i[0] = mn0; m_i[1] = mn1;

        float rs0 = 0.0f, rs1 = 0.0f;
#pragma unroll
        for (int nt = 0; nt < 8; nt++) {
            float p0 = __expf(S[nt][0] - mn0);
            float p1 = __expf(S[nt][1] - mn0);
            float p2 = __expf(S[nt][2] - mn1);
            float p3 = __expf(S[nt][3] - mn1);
            rs0 += p0 + p1; rs1 += p2 + p3;
            int cb = nt * 8 + 2 * tq;
            *(uint2*)&Ps[(w * 16 + g) * KSTR + cb]     = make_uint2(f2tf(p0), f2tf(p1));
            *(uint2*)&Ps[(w * 16 + g + 8) * KSTR + cb] = make_uint2(f2tf(p2), f2tf(p3));
        }
        rs0 += __shfl_xor_sync(0xffffffffu, rs0, 1);
        rs0 += __shfl_xor_sync(0xffffffffu, rs0, 2);
        rs1 += __shfl_xor_sync(0xffffffffu, rs1, 1);
        rs1 += __shfl_xor_sync(0xffffffffu, rs1, 2);

        l_i[0] = l_i[0] * c0 + rs0;
        l_i[1] = l_i[1] * c1 + rs1;
#pragma unroll
        for (int nt = 0; nt < 8; nt++) {
            O[nt][0] *= c0; O[nt][1] *= c0;
            O[nt][2] *= c1; O[nt][3] *= c1;
        }
        __syncwarp();   // P visible within warp (Ps rows are warp-private)

#pragma unroll
        for (int kk = 0; kk < 8; kk++) {
            uint32_t pa[4];
            int rb = (w * 16 + g) * KSTR + kk * 8;
            pa[0] = Ps[rb + tq];
            pa[1] = Ps[rb + 8 * KSTR + tq];
            pa[2] = Ps[rb + tq + 4];
            pa[3] = Ps[rb + 8 * KSTR + tq + 4];
#pragma unroll
            for (int nt = 0; nt < 8; nt++) {
                uint32_t vb[2];
                vb[0] = Vs[(kk * 8 + tq) * VSTR + nt * 8 + g];
                vb[1] = Vs[(kk * 8 + tq + 4) * VSTR + nt * 8 + g];
                mma_tf32(O[nt], pa, vb);
            }
        }
        __syncthreads();   // protect this stage before next iter's issue overwrites it
    }

    // Epilogue: normalize, write hi/lo bf16 split of Z directly
    float inv0 = 1.0f / l_i[0], inv1 = 1.0f / l_i[1];
    int m = b * SS + qt * 64 + w * 16 + g;
#pragma unroll
    for (int nt = 0; nt < 8; nt++) {
        int c = h * 64 + nt * 8 + 2 * tq;
        float v00 = O[nt][0] * inv0, v01 = O[nt][1] * inv0;
        float v10 = O[nt][2] * inv1, v11 = O[nt][3] * inv1;
        __nv_bfloat16 h00,l00,h01,l01,h10,l10,h11,l11;
        bsplit(v00,h00,l00); bsplit(v01,h01,l01);
        bsplit(v10,h10,l10); bsplit(v11,h11,l11);
        *(__nv_bfloat162*)&g_Zh[(size_t)m * DD + c]       = __nv_bfloat162(h00,h01);
        *(__nv_bfloat162*)&g_Zl[(size_t)m * DD + c]       = __nv_bfloat162(l00,l01);
        *(__nv_bfloat162*)&g_Zh[(size_t)(m + 8) * DD + c] = __nv_bfloat162(h10,h11);
        *(__nv_bfloat162*)&g_Zl[(size_t)(m + 8) * DD + c] = __nv_bfloat162(l10,l11);
    }
}

// ---------------------------------------------------------------------------
extern "C" void kernel_launch(void* const* d_in, const int* in_sizes, int n_in,
                              void* d_out, int out_size)
{
    (void)in_sizes; (void)n_in; (void)out_size;
    const float* x  = (const float*)d_in[0];
    const float* Wq = (const float*)d_in[1];
    const float* bq = (const float*)d_in[2];
    const float* Wk = (const float*)d_in[3];
    const float* bk = (const float*)d_in[4];
    const float* Wv = (const float*)d_in[5];
    const float* Wo = (const float*)d_in[6];
    const float* bv = (const float*)d_in[7];
    const float* bo = (const float*)d_in[8];
    float* out = (float*)d_out;

    cudaFuncSetAttribute(flash_kernel,
                         cudaFuncAttributeMaxDynamicSharedMemorySize, FLASH_SMEM);
    cudaFuncSetAttribute(gemm_bf16x3,
                         cudaFuncAttributeMaxDynamicSharedMemorySize, GEMM_SMEM);

    __nv_bfloat16 *Xh, *Xl, *Wth, *Wtl, *Zh, *Zl, *Woth, *Wotl;
    float *bias_d, *qkv_d;
    cudaGetSymbolAddress((void**)&Xh,   g_Xh);
    cudaGetSymbolAddress((void**)&Xl,   g_Xl);
    cudaGetSymbolAddress((void**)&Wth,  g_Wth);
    cudaGetSymbolAddress((void**)&Wtl,  g_Wtl);
    cudaGetSymbolAddress((void**)&Zh,   g_Zh);
    cudaGetSymbolAddress((void**)&Zl,   g_Zl);
    cudaGetSymbolAddress((void**)&Woth, g_Woth);
    cudaGetSymbolAddress((void**)&Wotl, g_Wotl);
    cudaGetSymbolAddress((void**)&bias_d, g_bias);
    cudaGetSymbolAddress((void**)&qkv_d,  g_QKV);

    // fused pre-pass
    prep_all<<<5136, 256>>>(x, Wq, Wk, Wv, Wo, bq, bk, bv, bo);

    // QKV projection (outputs rounded to tf32 bit patterns)
    gemm_bf16x3<<<dim3(24, 32), 256, GEMM_SMEM>>>(Xh, Xl, Wth, Wtl, bias_d, qkv_d, NQKV, 1);
    // attention (writes Zh/Zl split directly)
    flash_kernel<<<dim3(32, HH, BB), 128, FLASH_SMEM>>>();
    // output projection
    gemm_bf16x3<<<dim3(8, 32), 256, GEMM_SMEM>>>(Zh, Zl, Woth, Wotl, bias_d + NQKV, out, DD, 0);
}

// round 17
// speedup vs baseline: 1.4102x; 1.2500x over previous
#include <cuda_runtime.h>
#include <cuda_bf16.h>
#include <cuda_fp16.h>
#include <cstdint>

// Problem dims (fixed for this dataset)
#define BB   2
#define SS   2048
#define DD   1024
#define HH   16
#define DHD  64
#define MM   (BB*SS)      // 4096 rows
#define NQKV 3072

// Scratch (allocation-free rule: __device__ globals)
__device__ float    g_QKV[MM*NQKV];     // fused Q|K|V (tf32-rounded), stride 3072
__device__ __half   g_Xh[MM*DD];                      // fp16(x)
__device__ __half   g_Zh[MM*DD];                      // fp16(Z)
__device__ __half   g_Wth[NQKV*DD], g_Wtl[NQKV*DD];   // (32*W_qkv)^T [n][k] hi/lo
__device__ __half   g_Woth[DD*DD],  g_Wotl[DD*DD];    // (32*W_O)^T   [n][k] hi/lo
__device__ float    g_bias[NQKV + DD];

// ---------------------------------------------------------------------------
// helpers
// ---------------------------------------------------------------------------
__device__ __forceinline__ void hsplit(float v, __half &h, __half &l) {
    h = __float2half_rn(v);
    l = __float2half_rn(v - __half2float(h));
}
__device__ __forceinline__ uint32_t f2tf(float v) {
    uint32_t r; asm("cvt.rna.tf32.f32 %0, %1;" : "=r"(r) : "f"(v)); return r;
}
__device__ __forceinline__ void mma_tf32(float* d, const uint32_t* a, const uint32_t* b) {
    asm volatile(
        "mma.sync.aligned.m16n8k8.row.col.f32.tf32.tf32.f32 "
        "{%0,%1,%2,%3}, {%4,%5,%6,%7}, {%8,%9}, {%0,%1,%2,%3};\n"
        : "+f"(d[0]), "+f"(d[1]), "+f"(d[2]), "+f"(d[3])
        : "r"(a[0]), "r"(a[1]), "r"(a[2]), "r"(a[3]), "r"(b[0]), "r"(b[1]));
}
__device__ __forceinline__ void mma_f16(float* d, const uint32_t* a, const uint32_t* b) {
    asm volatile(
        "mma.sync.aligned.m16n8k16.row.col.f32.f16.f16.f32 "
        "{%0,%1,%2,%3}, {%4,%5,%6,%7}, {%8,%9}, {%0,%1,%2,%3};\n"
        : "+f"(d[0]), "+f"(d[1]), "+f"(d[2]), "+f"(d[3])
        : "r"(a[0]), "r"(a[1]), "r"(a[2]), "r"(a[3]), "r"(b[0]), "r"(b[1]));
}
__device__ __forceinline__ void ldm4(uint32_t* r, uint32_t addr) {
    asm volatile("ldmatrix.sync.aligned.m8n8.x4.shared.b16 {%0,%1,%2,%3}, [%4];"
                 : "=r"(r[0]), "=r"(r[1]), "=r"(r[2]), "=r"(r[3]) : "r"(addr));
}
__device__ __forceinline__ uint32_t smem_u32(const void* p) {
    uint32_t a;
    asm("{ .reg .u64 t; cvta.to.shared.u64 t, %1; cvt.u32.u64 %0, t; }" : "=r"(a) : "l"(p));
    return a;
}

// ---------------------------------------------------------------------------
// Fused pre-pass: x->fp16 / W_qkv split / W_O split / bias, one launch.
// Weights are scaled by exactly 32 (power of two) before fp16 split so the
// lo parts stay in fp16 normal range; GEMM epilogue multiplies by 1/32.
// block ranges: [0,4096) x, [4096,4864) wqkv, [4864,5120) wo, [5120,5136) bias
// ---------------------------------------------------------------------------
__global__ __launch_bounds__(256) void prep_all(
    const float* __restrict__ x,
    const float* __restrict__ Wq, const float* __restrict__ Wk, const float* __restrict__ Wv,
    const float* __restrict__ Wo,
    const float* __restrict__ bq, const float* __restrict__ bk,
    const float* __restrict__ bv, const float* __restrict__ bo)
{
    __shared__ float sm[64][65];
    const int bx = blockIdx.x;
    const int t  = threadIdx.x;

    if (bx < 4096) {
        int i = (bx * 256 + t) * 4;
        float4 v = *(const float4*)&x[i];
        *(__half2*)&g_Xh[i]     = __floats2half2_rn(v.x, v.y);
        *(__half2*)&g_Xh[i + 2] = __floats2half2_rn(v.z, v.w);
    } else if (bx < 4864) {
        int b2 = bx - 4096;                 // 16 k-blocks x 48 n-blocks
        int k0 = (b2 & 15) * 64;
        int n0 = (b2 >> 4) * 64;
        int which = n0 >> 10;
        int h = (n0 >> 6) & 15;
        const float* __restrict__ W = (which == 0) ? Wq : (which == 1) ? Wk : Wv;
#pragma unroll
        for (int i = 0; i < 16; i++) {
            int idx = t + i * 256;
            int r = idx >> 6, c = idx & 63;
            sm[r][c] = W[h * (DD * DHD) + (k0 + r) * DHD + c];
        }
        __syncthreads();
#pragma unroll
        for (int i = 0; i < 16; i++) {
            int idx = t + i * 256;
            int nl = idx >> 6, kl = idx & 63;
            __half hi, lo;
            hsplit(32.0f * sm[kl][nl], hi, lo);
            g_Wth[(n0 + nl) * DD + k0 + kl] = hi;
            g_Wtl[(n0 + nl) * DD + k0 + kl] = lo;
        }
    } else if (bx < 5120) {
        int b2 = bx - 4864;                 // 16 x 16
        int k0 = (b2 & 15) * 64;
        int n0 = (b2 >> 4) * 64;
#pragma unroll
        for (int i = 0; i < 16; i++) {
            int idx = t + i * 256;
            int r = idx >> 6, c = idx & 63;
            sm[r][c] = Wo[(k0 + r) * DD + n0 + c];
        }
        __syncthreads();
#pragma unroll
        for (int i = 0; i < 16; i++) {
            int idx = t + i * 256;
            int nl = idx >> 6, kl = idx & 63;
            __half hi, lo;
            hsplit(32.0f * sm[kl][nl], hi, lo);
            g_Woth[(n0 + nl) * DD + k0 + kl] = hi;
            g_Wotl[(n0 + nl) * DD + k0 + kl] = lo;
        }
    } else {
        int id = (bx - 5120) * 256 + t;     // 0..4095
        if (id < NQKV) {
            int which = id >> 10, n = id & 1023;
            g_bias[id] = (which == 0) ? bq[n] : (which == 1) ? bk[n] : bv[n];
        } else {
            int n = id - NQKV;
            float s = 0.0f;
#pragma unroll
            for (int h = 0; h < HH; h++) s += bo[h * DD + n];
            g_bias[id] = s;
        }
    }
}

// ---------------------------------------------------------------------------
// fp16 2-pass GEMM: C[m,n] = (1/32) * sum_k Ah[m,k]*(Bh+Bl)[n,k] + bias[n]
// A rounded to fp16 (error ~2^-12.6 rms); B = 32*W split hi/lo (near-exact).
// Block 128x128, BK=32, 8 warps, cp.async double buffer, ldmatrix.x4.
// __launch_bounds__(256, 2): 2 CTAs/SM. Stage = 3 arrays x 128 x 20 u32.
// round_out != 0: round stores to tf32 bit patterns (Q/K/V feeding flash).
// ---------------------------------------------------------------------------
#define GSTG 7680                       // u32 per stage (3 arrays x 128*20)
#define GEMM_SMEM (2 * GSTG * 4)        // 61440 B

__global__ __launch_bounds__(256, 2) void gemm_f16x2(
    const __half* __restrict__ Ah,
    const __half* __restrict__ Bh, const __half* __restrict__ Bl,
    const float* __restrict__ bias, float* __restrict__ C, int ldC, int round_out)
{
    extern __shared__ __align__(16) uint32_t sm[];
    const uint32_t smb = smem_u32(sm);

    const int n0   = blockIdx.x * 128;
    const int m0   = blockIdx.y * 128;
    const int t    = threadIdx.x;
    const int lane = t & 31, w = t >> 5;
    const int g    = lane >> 2, tq = lane & 3;
    const int wm   = w & 1, wn = w >> 1;

    const int a_row_l = ((lane >> 3) & 1) * 8 + (lane & 7);
    const int a_col_l = (lane >> 4) * 4;
    const int b_row_l = (lane >> 4) * 8 + (lane & 7);
    const int b_col_l = ((lane >> 3) & 1) * 4;

    const __half* srcs[3] = { Ah + (size_t)m0 * DD,
                              Bh + (size_t)n0 * DD, Bl + (size_t)n0 * DD };

    float acc[4][4][4];
#pragma unroll
    for (int mt = 0; mt < 4; mt++)
#pragma unroll
        for (int nt = 0; nt < 4; nt++)
#pragma unroll
            for (int i = 0; i < 4; i++) acc[mt][nt][i] = 0.0f;

#pragma unroll
    for (int i = 0; i < 6; i++) {
        int id = t + i * 256;                 // 0..1535
        int which = id >> 9, r = (id >> 2) & 127, c = id & 3;
        const __half* gp = srcs[which] + (size_t)r * DD + c * 8;
        uint32_t sa = smb + (which * 2560 + r * 20 + c * 4) * 4;
        asm volatile("cp.async.cg.shared.global [%0], [%1], 16;" :: "r"(sa), "l"(gp));
    }
    asm volatile("cp.async.commit_group;" ::: "memory");

    for (int kt = 0; kt < 32; kt++) {
        asm volatile("cp.async.wait_group 0;" ::: "memory");
        __syncthreads();

        if (kt + 1 < 32) {
            int k0n = (kt + 1) * 32;
            uint32_t stoff = ((kt + 1) & 1) * GSTG;
#pragma unroll
            for (int i = 0; i < 6; i++) {
                int id = t + i * 256;
                int which = id >> 9, r = (id >> 2) & 127, c = id & 3;
                const __half* gp = srcs[which] + (size_t)r * DD + k0n + c * 8;
                uint32_t sa = smb + (stoff + which * 2560 + r * 20 + c * 4) * 4;
                asm volatile("cp.async.cg.shared.global [%0], [%1], 16;" :: "r"(sa), "l"(gp));
            }
            asm volatile("cp.async.commit_group;" ::: "memory");
        }

        const uint32_t st = (kt & 1) * GSTG;
#pragma unroll
        for (int kk = 0; kk < 2; kk++) {
            uint32_t ah[4][4], bh[2][4], bl[2][4];
#pragma unroll
            for (int mt = 0; mt < 4; mt++) {
                uint32_t off = (st + (wm * 64 + mt * 16 + a_row_l) * 20 + kk * 8 + a_col_l) * 4;
                ldm4(ah[mt], smb + off);
            }
#pragma unroll
            for (int p = 0; p < 2; p++) {
                uint32_t off = (st + 2560 + (wn * 32 + p * 16 + b_row_l) * 20 + kk * 8 + b_col_l) * 4;
                ldm4(bh[p], smb + off);
                ldm4(bl[p], smb + off + 2560 * 4);
            }
#pragma unroll
            for (int mt = 0; mt < 4; mt++)
#pragma unroll
                for (int nt = 0; nt < 4; nt++)
                    mma_f16(acc[mt][nt], ah[mt], &bh[nt >> 1][(nt & 1) * 2]);
#pragma unroll
            for (int mt = 0; mt < 4; mt++)
#pragma unroll
                for (int nt = 0; nt < 4; nt++)
                    mma_f16(acc[mt][nt], ah[mt], &bl[nt >> 1][(nt & 1) * 2]);
        }
    }

    const float wsc = 0.03125f;   // undo the exact 32x weight scaling
#pragma unroll
    for (int mt = 0; mt < 4; mt++) {
        int m = m0 + wm * 64 + mt * 16 + g;
#pragma unroll
        for (int nt = 0; nt < 4; nt++) {
            int n = n0 + wn * 32 + nt * 8 + 2 * tq;
            float b0 = bias[n], b1 = bias[n + 1];
            float v00 = acc[mt][nt][0] * wsc + b0, v01 = acc[mt][nt][1] * wsc + b1;
            float v10 = acc[mt][nt][2] * wsc + b0, v11 = acc[mt][nt][3] * wsc + b1;
            if (round_out) {
                v00 = __uint_as_float(f2tf(v00)); v01 = __uint_as_float(f2tf(v01));
                v10 = __uint_as_float(f2tf(v10)); v11 = __uint_as_float(f2tf(v11));
            }
            *(float2*)&C[(size_t)m * ldC + n]       = make_float2(v00, v01);
            *(float2*)&C[(size_t)(m + 8) * ldC + n] = make_float2(v10, v11);
        }
    }
}

// ---------------------------------------------------------------------------
// Flash attention (causal), tf32 mma. 64-row Q tiles, 4 warps (128 thr),
// cp.async double-buffered K/V (raw tf32 bit patterns), 2 CTAs/SM.
// Epilogue writes fp16 Z directly.
// ---------------------------------------------------------------------------
#define KSTR 68
#define VSTR 72
#define KVSTG (64*KSTR + 64*VSTR)                 // 8960 u32 per stage
#define FLASH_SMEM ((2*KVSTG + 64*KSTR) * 4)      // 89088 B

__global__ __launch_bounds__(128, 2) void flash_kernel()
{
    extern __shared__ __align__(16) uint32_t sm[];
    uint32_t* Ps = sm + 2 * KVSTG;                // [64][68]

    const int qt = 31 - blockIdx.x;               // big tiles first
    const int h = blockIdx.y, b = blockIdx.z;
    const int t = threadIdx.x, lane = t & 31, w = t >> 5;
    const int g = lane >> 2, tq = lane & 3;
    const float scale = 0.125f;
    const int jc = qt + 1;
    const uint32_t smb = smem_u32(sm);

    const size_t rowbase = (size_t)(b * SS) * NQKV;
    const int qoff = h * 64, koff = 1024 + h * 64, voff = 2048 + h * 64;

    auto issue_kv = [&](int j, int s) {
        uint32_t base = smb + (uint32_t)(s * KVSTG) * 4;
#pragma unroll
        for (int i = 0; i < 16; i++) {
            int id = t + i * 128;                 // 0..2047
            int which = id >> 10;                 // 0=K, 1=V
            int rem = id & 1023;
            int r = rem >> 4, c4 = (rem & 15) * 4;
            const float* gp;
            uint32_t sa;
            if (which == 0) {
                gp = &g_QKV[rowbase + (size_t)(j * 64 + r) * NQKV + koff + c4];
                sa = base + (uint32_t)(r * KSTR + c4) * 4;
            } else {
                gp = &g_QKV[rowbase + (size_t)(j * 64 + r) * NQKV + voff + c4];
                sa = base + (uint32_t)(64 * KSTR + r * VSTR + c4) * 4;
            }
            asm volatile("cp.async.cg.shared.global [%0], [%1], 16;" :: "r"(sa), "l"(gp));
        }
        asm volatile("cp.async.commit_group;" ::: "memory");
    };

    issue_kv(0, 0);
#pragma unroll
    for (int i = 0; i < 8; i++) {
        int id = t + i * 128;                     // 0..1023
        int r = id >> 4, c4 = (id & 15) * 4;
        uint4 v = *(const uint4*)&g_QKV[rowbase + (size_t)(qt * 64 + r) * NQKV + qoff + c4];
        *(uint4*)&Ps[r * KSTR + c4] = v;
    }
    __syncthreads();

    uint32_t qa[8][4];
    {
        int rb = (w * 16 + g) * KSTR;
#pragma unroll
        for (int kk = 0; kk < 8; kk++) {
            qa[kk][0] = Ps[rb + kk * 8 + tq];
            qa[kk][1] = Ps[rb + 8 * KSTR + kk * 8 + tq];
            qa[kk][2] = Ps[rb + kk * 8 + tq + 4];
            qa[kk][3] = Ps[rb + 8 * KSTR + kk * 8 + tq + 4];
        }
    }

    float m_i[2] = {-1e30f, -1e30f}, l_i[2] = {0.0f, 0.0f};
    float O[8][4];
#pragma unroll
    for (int nt = 0; nt < 8; nt++)
#pragma unroll
        for (int i = 0; i < 4; i++) O[nt][i] = 0.0f;

    for (int j = 0; j < jc; j++) {
        if (j + 1 < jc) {
            issue_kv(j + 1, (j + 1) & 1);
            asm volatile("cp.async.wait_group 1;" ::: "memory");
        } else {
            asm volatile("cp.async.wait_group 0;" ::: "memory");
        }
        __syncthreads();

        const uint32_t* Ks = sm + (j & 1) * KVSTG;
        const uint32_t* Vs = Ks + 64 * KSTR;

        float S[8][4];
#pragma unroll
        for (int nt = 0; nt < 8; nt++)
#pragma unroll
            for (int i = 0; i < 4; i++) S[nt][i] = 0.0f;

#pragma unroll
        for (int kk = 0; kk < 8; kk++) {
#pragma unroll
            for (int nt = 0; nt < 8; nt++) {
                uint32_t kb[2];
                kb[0] = Ks[(nt * 8 + g) * KSTR + kk * 8 + tq];
                kb[1] = Ks[(nt * 8 + g) * KSTR + kk * 8 + tq + 4];
                mma_tf32(S[nt], qa[kk], kb);
            }
        }

        if (j == qt) {
            int r0 = w * 16 + g, r1 = r0 + 8;
#pragma unroll
            for (int nt = 0; nt < 8; nt++) {
                int c = nt * 8 + 2 * tq;
                S[nt][0] = (c     <= r0) ? S[nt][0] * scale : -1e30f;
                S[nt][1] = (c + 1 <= r0) ? S[nt][1] * scale : -1e30f;
                S[nt][2] = (c     <= r1) ? S[nt][2] * scale : -1e30f;
                S[nt][3] = (c + 1 <= r1) ? S[nt][3] * scale : -1e30f;
            }
        } else {
#pragma unroll
            for (int nt = 0; nt < 8; nt++)
#pragma unroll
                for (int i = 0; i < 4; i++) S[nt][i] *= scale;
        }

        float mx0 = -1e30f, mx1 = -1e30f;
#pragma unroll
        for (int nt = 0; nt < 8; nt++) {
            mx0 = fmaxf(mx0, fmaxf(S[nt][0], S[nt][1]));
            mx1 = fmaxf(mx1, fmaxf(S[nt][2], S[nt][3]));
        }
        mx0 = fmaxf(mx0, __shfl_xor_sync(0xffffffffu, mx0, 1));
        mx0 = fmaxf(mx0, __shfl_xor_sync(0xffffffffu, mx0, 2));
        mx1 = fmaxf(mx1, __shfl_xor_sync(0xffffffffu, mx1, 1));
        mx1 = fmaxf(mx1, __shfl_xor_sync(0xffffffffu, mx1, 2));

        float mn0 = fmaxf(m_i[0], mx0), mn1 = fmaxf(m_i[1], mx1);
        float c0 = __expf(m_i[0] - mn0), c1 = __expf(m_i[1] - mn1);
        m_i[0] = mn0; m_i[1] = mn1;

        float rs0 = 0.0f, rs1 = 0.0f;
#pragma unroll
        for (int nt = 0; nt < 8; nt++) {
            float p0 = __expf(S[nt][0] - mn0);
            float p1 = __expf(S[nt][1] - mn0);
            float p2 = __expf(S[nt][2] - mn1);
            float p3 = __expf(S[nt][3] - mn1);
            rs0 += p0 + p1; rs1 += p2 + p3;
            int cb = nt * 8 + 2 * tq;
            *(uint2*)&Ps[(w * 16 + g) * KSTR + cb]     = make_uint2(f2tf(p0), f2tf(p1));
            *(uint2*)&Ps[(w * 16 + g + 8) * KSTR + cb] = make_uint2(f2tf(p2), f2tf(p3));
        }
        rs0 += __shfl_xor_sync(0xffffffffu, rs0, 1);
        rs0 += __shfl_xor_sync(0xffffffffu, rs0, 2);
        rs1 += __shfl_xor_sync(0xffffffffu, rs1, 1);
        rs1 += __shfl_xor_sync(0xffffffffu, rs1, 2);

        l_i[0] = l_i[0] * c0 + rs0;
        l_i[1] = l_i[1] * c1 + rs1;
#pragma unroll
        for (int nt = 0; nt < 8; nt++) {
            O[nt][0] *= c0; O[nt][1] *= c0;
            O[nt][2] *= c1; O[nt][3] *= c1;
        }
        __syncwarp();   // P visible within warp (Ps rows are warp-private)

#pragma unroll
        for (int kk = 0; kk < 8; kk++) {
            uint32_t pa[4];
            int rb = (w * 16 + g) * KSTR + kk * 8;
            pa[0] = Ps[rb + tq];
            pa[1] = Ps[rb + 8 * KSTR + tq];
            pa[2] = Ps[rb + tq + 4];
            pa[3] = Ps[rb + 8 * KSTR + tq + 4];
#pragma unroll
            for (int nt = 0; nt < 8; nt++) {
                uint32_t vb[2];
                vb[0] = Vs[(kk * 8 + tq) * VSTR + nt * 8 + g];
                vb[1] = Vs[(kk * 8 + tq + 4) * VSTR + nt * 8 + g];
                mma_tf32(O[nt], pa, vb);
            }
        }
        __syncthreads();   // protect this stage before next iter's issue overwrites it
    }

    // Epilogue: normalize, write fp16 Z directly
    float inv0 = 1.0f / l_i[0], inv1 = 1.0f / l_i[1];
    int m = b * SS + qt * 64 + w * 16 + g;
#pragma unroll
    for (int nt = 0; nt < 8; nt++) {
        int c = h * 64 + nt * 8 + 2 * tq;
        *(__half2*)&g_Zh[(size_t)m * DD + c] =
            __floats2half2_rn(O[nt][0] * inv0, O[nt][1] * inv0);
        *(__half2*)&g_Zh[(size_t)(m + 8) * DD + c] =
            __floats2half2_rn(O[nt][2] * inv1, O[nt][3] * inv1);
    }
}

// ---------------------------------------------------------------------------
extern "C" void kernel_launch(void* const* d_in, const int* in_sizes, int n_in,
                              void* d_out, int out_size)
{
    (void)in_sizes; (void)n_in; (void)out_size;
    const float* x  = (const float*)d_in[0];
    const float* Wq = (const float*)d_in[1];
    const float* bq = (const float*)d_in[2];
    const float* Wk = (const float*)d_in[3];
    const float* bk = (const float*)d_in[4];
    const float* Wv = (const float*)d_in[5];
    const float* Wo = (const float*)d_in[6];
    const float* bv = (const float*)d_in[7];
    const float* bo = (const float*)d_in[8];
    float* out = (float*)d_out;

    cudaFuncSetAttribute(flash_kernel,
                         cudaFuncAttributeMaxDynamicSharedMemorySize, FLASH_SMEM);
    cudaFuncSetAttribute(gemm_f16x2,
                         cudaFuncAttributeMaxDynamicSharedMemorySize, GEMM_SMEM);

    __half *Xh, *Wth, *Wtl, *Zh, *Woth, *Wotl;
    float *bias_d, *qkv_d;
    cudaGetSymbolAddress((void**)&Xh,   g_Xh);
    cudaGetSymbolAddress((void**)&Wth,  g_Wth);
    cudaGetSymbolAddress((void**)&Wtl,  g_Wtl);
    cudaGetSymbolAddress((void**)&Zh,   g_Zh);
    cudaGetSymbolAddress((void**)&Woth, g_Woth);
    cudaGetSymbolAddress((void**)&Wotl, g_Wotl);
    cudaGetSymbolAddress((void**)&bias_d, g_bias);
    cudaGetSymbolAddress((void**)&qkv_d,  g_QKV);

    // fused pre-pass
    prep_all<<<5136, 256>>>(x, Wq, Wk, Wv, Wo, bq, bk, bv, bo);

    // QKV projection (outputs rounded to tf32 bit patterns)
    gemm_f16x2<<<dim3(24, 32), 256, GEMM_SMEM>>>(Xh, Wth, Wtl, bias_d, qkv_d, NQKV, 1);
    // attention (writes fp16 Z directly)
    flash_kernel<<<dim3(32, HH, BB), 128, FLASH_SMEM>>>();
    // output projection
    gemm_f16x2<<<dim3(8, 32), 256, GEMM_SMEM>>>(Zh, Woth, Wotl, bias_d + NQKV, out, DD, 0);
}